// round 3
// baseline (speedup 1.0000x reference)
#include <cuda_runtime.h>
#include <cuda_bf16.h>

// Problem constants
#define NB   16
#define NCIN 64
#define H1   128
#define H2   256
#define Q1   64
#define Q2   16

// Tiling
#define TH   64
#define TW   32
#define CC   4
#define SP   35     // smem row stride in floats: odd => conflict-free (see analysis)

typedef unsigned long long ull;

// Scratch (allocation-free rule: __device__ globals)
__device__ float  g_up[(size_t)NB * NCIN * H2 * H2];          // 256 MB intermediate
__device__ float4 g_wpre [Q1 * NCIN * 9];
__device__ float4 g_wpost[Q2 * NCIN * 9];

// ---------------- packed f32x2 helpers (Blackwell FFMA2) ----------------
__device__ __forceinline__ ull ffma2(ull a, ull b, ull c) {
    ull d;
    asm("fma.rn.f32x2 %0, %1, %2, %3;" : "=l"(d) : "l"(a), "l"(b), "l"(c));
    return d;
}
__device__ __forceinline__ ull pack2(float x) {
    ull d; asm("mov.b64 %0, {%1, %1};" : "=l"(d) : "f"(x)); return d;
}
__device__ __forceinline__ ull pack2f(float x, float y) {
    ull d; asm("mov.b64 %0, {%1, %2};" : "=l"(d) : "f"(x), "f"(y)); return d;
}
__device__ __forceinline__ float2 unpack2(ull v) {
    float2 r; asm("mov.b64 {%0, %1}, %2;" : "=f"(r.x), "=f"(r.y) : "l"(v)); return r;
}

// ---------------- weight reorder ----------------
__global__ void reorder_pre(const float* __restrict__ w) {
    int i = blockIdx.x * blockDim.x + threadIdx.x;
    if (i >= Q1 * NCIN * 9) return;
    int k = i % 9, cin = (i / 9) % NCIN, q = i / (9 * NCIN);
    float4 v;
    v.x = w[(((q      ) * NCIN + cin) * 9) + k];
    v.y = w[(((q +  64) * NCIN + cin) * 9) + k];
    v.z = w[(((q + 128) * NCIN + cin) * 9) + k];
    v.w = w[(((q + 192) * NCIN + cin) * 9) + k];
    g_wpre[i] = v;
}
__global__ void reorder_post(const float* __restrict__ w) {
    int i = blockIdx.x * blockDim.x + threadIdx.x;
    if (i >= Q2 * NCIN * 9) return;
    int k = i % 9, cin = (i / 9) % NCIN, q = i / (9 * NCIN);
    float4 v;
    v.x = w[(((4*q + 0) * NCIN + cin) * 9) + k];
    v.y = w[(((4*q + 1) * NCIN + cin) * 9) + k];
    v.z = w[(((4*q + 2) * NCIN + cin) * 9) + k];
    v.w = w[(((4*q + 3) * NCIN + cin) * 9) + k];
    g_wpost[i] = v;
}

// ---------------------------------------------------------------------------
// Tiled 3x3 conv with FFMA2. Block: (b, quad), 64x32 tile, 256 threads.
// Thread: 1 out row x 8 cols x 4 channels = 16 packed fp32x2 accumulators.
// ---------------------------------------------------------------------------
template<int HIN, int Q, bool WAVELET>
__global__ __launch_bounds__(256, 2)
void conv3x3_q(const float* __restrict__ xp,
               const float* __restrict__ bias,
               float* __restrict__ outp)
{
    constexpr int WIN = HIN;
    __shared__ float  sIn[CC][TH + 2][SP];
    __shared__ float4 sW[NCIN * 9];

    const int tid = threadIdx.x;
    const int wt  = blockIdx.x;
    const int ht  = blockIdx.y;
    const int z   = blockIdx.z;
    const int b   = z / Q;
    const int q   = z % Q;
    const int h0  = ht * TH;
    const int w0b = wt * TW;

    const float4* wg = (WAVELET ? g_wpre : g_wpost) + q * NCIN * 9;
    for (int i = tid; i < NCIN * 9; i += 256) sW[i] = wg[i];

    const int ro  = tid >> 2;      // out row 0..63
    const int seg = tid & 3;       // col segment: cols 8*seg .. 8*seg+7
    const int c0  = seg * 8;

    ull acc01[8], acc23[8];
    {
        float b0, b1, b2, b3;
        if (WAVELET) { b0 = bias[q]; b1 = bias[q+64]; b2 = bias[q+128]; b3 = bias[q+192]; }
        else         { b0 = bias[4*q]; b1 = bias[4*q+1]; b2 = bias[4*q+2]; b3 = bias[4*q+3]; }
        ull i01 = pack2f(b0, b1), i23 = pack2f(b2, b3);
        #pragma unroll
        for (int p = 0; p < 8; ++p) { acc01[p] = i01; acc23[p] = i23; }
    }

    const float* x  = WAVELET ? xp : g_up;
    const float* xb = x + (size_t)b * NCIN * HIN * WIN;

    const int lr = tid >> 5;       // warp id 0..7 : loader row group
    const int lc = tid & 31;       // loader col

    for (int cc = 0; cc < NCIN / CC; ++cc) {
        __syncthreads();
        // ---- cooperative load: warp per row, lane per col (coalesced) ----
        #pragma unroll
        for (int ci = 0; ci < CC; ++ci) {
            const float* src = xb + (size_t)(cc * CC + ci) * HIN * WIN;
            for (int r = lr; r < TH + 2; r += 8) {
                int gh = h0 - 1 + r;
                bool hok = (gh >= 0) && (gh < HIN);
                for (int c = lc; c < TW + 2; c += 32) {
                    int gw = w0b - 1 + c;
                    float v = 0.0f;
                    if (hok && gw >= 0 && gw < WIN)
                        v = __ldg(&src[(size_t)gh * WIN + gw]);
                    sIn[ci][r][c] = v;
                }
            }
        }
        __syncthreads();

        // ---- compute: FFMA2 mainloop ----
        #pragma unroll
        for (int ci = 0; ci < CC; ++ci) {
            const float4* wrow = &sW[(cc * CC + ci) * 9];
            #pragma unroll
            for (int jj = 0; jj < 3; ++jj) {      // input row ro+jj (padded)
                ull xp2[10];
                #pragma unroll
                for (int u = 0; u < 10; ++u)
                    xp2[u] = pack2(sIn[ci][ro + jj][c0 + u]);
                #pragma unroll
                for (int kw = 0; kw < 3; ++kw) {
                    float4 wv = wrow[jj * 3 + kw];
                    ull w01 = pack2f(wv.x, wv.y);
                    ull w23 = pack2f(wv.z, wv.w);
                    #pragma unroll
                    for (int p = 0; p < 8; ++p) {
                        acc01[p] = ffma2(xp2[p + kw], w01, acc01[p]);
                        acc23[p] = ffma2(xp2[p + kw], w23, acc23[p]);
                    }
                }
            }
        }
    }

    // ------------------------- epilogue -------------------------
    const int gh   = h0  + ro;
    const int ocol = w0b + c0;

    if (WAVELET) {
        float* up = g_up + (size_t)(b * NCIN + q) * (2 * HIN) * (2 * WIN);
        const size_t base0 = (size_t)(2 * gh) * (2 * WIN);
        const size_t base1 = base0 + (2 * WIN);
        #pragma unroll
        for (int p = 0; p < 8; p += 2) {
            float2 v01a = unpack2(acc01[p]);      // ll, lh
            float2 v23a = unpack2(acc23[p]);      // hl, hh
            float2 v01b = unpack2(acc01[p + 1]);
            float2 v23b = unpack2(acc23[p + 1]);
            float ee0 = 0.5f * (v01a.x + v01a.y + v23a.x + v23a.y);
            float eo0 = 0.5f * (v01a.x - v01a.y + v23a.x - v23a.y);
            float oe0 = 0.5f * (v01a.x + v01a.y - v23a.x - v23a.y);
            float oo0 = 0.5f * (v01a.x - v01a.y - v23a.x + v23a.y);
            float ee1 = 0.5f * (v01b.x + v01b.y + v23b.x + v23b.y);
            float eo1 = 0.5f * (v01b.x - v01b.y + v23b.x - v23b.y);
            float oe1 = 0.5f * (v01b.x + v01b.y - v23b.x - v23b.y);
            float oo1 = 0.5f * (v01b.x - v01b.y - v23b.x + v23b.y);
            int gw2 = 2 * (ocol + p);
            *(float4*)&up[base0 + gw2] = make_float4(ee0, eo0, ee1, eo1);
            *(float4*)&up[base1 + gw2] = make_float4(oe0, oo0, oe1, oo1);
        }
    } else {
        #pragma unroll
        for (int c = 0; c < 4; ++c) {
            float v[8];
            #pragma unroll
            for (int p = 0; p < 8; ++p) {
                float2 t = (c < 2) ? unpack2(acc01[p]) : unpack2(acc23[p]);
                v[p] = (c & 1) ? t.y : t.x;
            }
            float* dst = outp + (size_t)(b * (4 * Q) + 4 * q + c) * HIN * WIN
                              + (size_t)gh * WIN + ocol;
            *(float4*)&dst[0] = make_float4(v[0], v[1], v[2], v[3]);
            *(float4*)&dst[4] = make_float4(v[4], v[5], v[6], v[7]);
        }
    }
}

extern "C" void kernel_launch(void* const* d_in, const int* in_sizes, int n_in,
                              void* d_out, int out_size)
{
    (void)in_sizes; (void)n_in; (void)out_size;
    const float* x      = (const float*)d_in[0];
    const float* w_pre  = (const float*)d_in[1];
    const float* b_pre  = (const float*)d_in[2];
    const float* w_post = (const float*)d_in[3];
    const float* b_post = (const float*)d_in[4];
    float* out = (float*)d_out;

    reorder_pre <<<(Q1 * NCIN * 9 + 255) / 256, 256>>>(w_pre);
    reorder_post<<<(Q2 * NCIN * 9 + 255) / 256, 256>>>(w_post);

    {   // conv_pre + wavelet upsample -> g_up
        dim3 grid(H1 / TW, H1 / TH, NB * Q1);   // (4, 2, 1024)
        conv3x3_q<H1, Q1, true><<<grid, 256>>>(x, b_pre, nullptr);
    }
    {   // conv_post: g_up -> out
        dim3 grid(H2 / TW, H2 / TH, NB * Q2);   // (8, 4, 256)
        conv3x3_q<H2, Q2, false><<<grid, 256>>>(nullptr, b_post, out);
    }
}

// round 5
// speedup vs baseline: 5.1698x; 5.1698x over previous
#include <cuda_runtime.h>
#include <cstdint>

#define NB 16
#define CI 64
#define KTOT 576     // 9 taps * 64 cin

// ---------------- device scratch (no allocs allowed) ----------------
__device__ float g_up[(size_t)NB * CI * 256 * 256];     // 256 MB intermediate
__device__ float g_wpre_hi[256 * KTOT];                 // quad-interleaved rows
__device__ float g_wpre_lo[256 * KTOT];
__device__ float g_wpost_hi[64 * KTOT];
__device__ float g_wpost_lo[64 * KTOT];

__device__ __forceinline__ uint32_t tf32r(float x) {
    uint32_t r; asm("cvt.rna.tf32.f32 %0, %1;" : "=r"(r) : "f"(x)); return r;
}

// m16n8k8 tf32 MMA, fp32 accumulate (sm_80+ baseline instruction -> tensor pipe)
__device__ __forceinline__ void mma8(float* c, const uint32_t a[4],
                                     uint32_t b0, uint32_t b1) {
    asm volatile(
        "mma.sync.aligned.m16n8k8.row.col.f32.tf32.tf32.f32 "
        "{%0,%1,%2,%3}, {%4,%5,%6,%7}, {%8,%9}, {%0,%1,%2,%3};"
        : "+f"(c[0]), "+f"(c[1]), "+f"(c[2]), "+f"(c[3])
        : "r"(a[0]), "r"(a[1]), "r"(a[2]), "r"(a[3]), "r"(b0), "r"(b1));
}

// ---------------- weight reorder + hi/lo tf32 split ----------------
// pre rows: R = 4q+s  <->  conv channel ch = s*64+q ; k = tap*64 + cin
__global__ void reorder_pre(const float* __restrict__ w) {
    int i = blockIdx.x * blockDim.x + threadIdx.x;
    if (i >= 256 * KTOT) return;
    int k = i % KTOT, R = i / KTOT;
    int t = k / 64, ci = k % 64;
    int ch = (R & 3) * 64 + (R >> 2);
    float v = w[((ch * 64 + ci) * 3 + t / 3) * 3 + (t % 3)];
    float hi = __uint_as_float(tf32r(v));
    g_wpre_hi[i] = hi;
    g_wpre_lo[i] = __uint_as_float(tf32r(v - hi));
}
__global__ void reorder_post(const float* __restrict__ w) {
    int i = blockIdx.x * blockDim.x + threadIdx.x;
    if (i >= 64 * KTOT) return;
    int k = i % KTOT, co = i / KTOT;
    int t = k / 64, ci = k % 64;
    float v = w[((co * 64 + ci) * 3 + t / 3) * 3 + (t % 3)];
    float hi = __uint_as_float(tf32r(v));
    g_wpost_hi[i] = hi;
    g_wpost_lo[i] = __uint_as_float(tf32r(v - hi));
}

// ---------------------------------------------------------------------------
// Implicit-GEMM conv via warp mma.sync (tf32, hi/lo weight split).
// Block: 256 thr = 8 warps (4 m-warps x 2 n-warps). M = 128 px of one row.
// Pre (WAVELET): NTILE=128 quad-interleaved channel rows, z = half index,
//                epilogue = wavelet recombine + 2x shuffle -> g_up.
// Post:          NTILE=64 channels, z = 128-px segment, plain store.
// ---------------------------------------------------------------------------
template<int W, int H, int NTILE, int NF, bool WAVELET>
__global__ __launch_bounds__(256, 2)
void conv_mma(const float* __restrict__ xin, const float* __restrict__ bias,
              float* __restrict__ outp)
{
    constexpr int CK = 16;                 // cin chunk
    __shared__ float sIn[3][CK][136];      // 8*ct+gr banks: conflict-free
    __shared__ float sW[2][NTILE][20];     // gr*20+ct banks: conflict-free

    const int tid  = threadIdx.x;
    const int lane = tid & 31;
    const int wid  = tid >> 5;
    const int wm   = wid & 3;              // m-warp: 32 px
    const int wn   = wid >> 2;             // n-warp: NF*8 channels
    const int gr   = lane >> 2;
    const int ct   = lane & 3;

    const int h   = blockIdx.x;
    const int b   = blockIdx.y;
    const int z   = blockIdx.z;
    const int px0 = WAVELET ? 0 : z * 128;
    const int mt  = WAVELET ? z : 0;

    const float* src = WAVELET ? xin : (const float*)g_up;
    const float* whi = WAVELET ? (g_wpre_hi + (size_t)mt * 128 * KTOT) : g_wpost_hi;
    const float* wlo = WAVELET ? (g_wpre_lo + (size_t)mt * 128 * KTOT) : g_wpost_lo;

    float acc[2][NF][4];
    #pragma unroll
    for (int mf = 0; mf < 2; ++mf)
        #pragma unroll
        for (int nf = 0; nf < NF; ++nf)
            #pragma unroll
            for (int u = 0; u < 4; ++u) acc[mf][nf][u] = 0.0f;

    for (int c0 = 0; c0 < CI; c0 += CK) {
        __syncthreads();
        // ---- stage 3 input rows x CK cins, tf32-rounded ----
        for (int i = tid; i < 3 * CK * 130; i += 256) {
            int p  = i % 130;
            int t2 = i / 130;
            int ci = t2 % CK;
            int r  = t2 / CK;
            int gh = h - 1 + r;
            int gw = px0 - 1 + p;
            float v = 0.0f;
            if (gh >= 0 && gh < H && gw >= 0 && gw < W)
                v = __ldg(&src[(((size_t)b * CI + c0 + ci) * H + gh) * (size_t)W + gw]);
            sIn[r][ci][p] = __uint_as_float(tf32r(v));
        }

        for (int t = 0; t < 9; ++t) {
            __syncthreads();
            // ---- stage weight tile (hi+lo) for this tap ----
            for (int i = tid; i < 2 * NTILE * CK; i += 256) {
                int k  = i % CK;
                int t2 = i / CK;
                int n  = t2 % NTILE;
                int hl = t2 / NTILE;
                const float* ws = hl ? wlo : whi;
                sW[hl][n][k] = __ldg(&ws[(size_t)n * KTOT + t * 64 + c0 + k]);
            }
            __syncthreads();

            const int rr  = t / 3;
            const int dwp = t % 3;         // px index offset = m + dw + 1 = m + t%3
            #pragma unroll
            for (int ks = 0; ks < 2; ++ks) {
                const int kb = ks * 8;
                uint32_t a[2][4];
                #pragma unroll
                for (int mf = 0; mf < 2; ++mf) {
                    const int px = wm * 32 + mf * 16 + gr + dwp;
                    a[mf][0] = __float_as_uint(sIn[rr][kb + ct    ][px]);
                    a[mf][1] = __float_as_uint(sIn[rr][kb + ct    ][px + 8]);
                    a[mf][2] = __float_as_uint(sIn[rr][kb + ct + 4][px]);
                    a[mf][3] = __float_as_uint(sIn[rr][kb + ct + 4][px + 8]);
                }
                #pragma unroll
                for (int hl = 0; hl < 2; ++hl) {
                    #pragma unroll
                    for (int nf = 0; nf < NF; ++nf) {
                        const int n = wn * (NF * 8) + nf * 8 + gr;
                        uint32_t b0 = __float_as_uint(sW[hl][n][kb + ct]);
                        uint32_t b1 = __float_as_uint(sW[hl][n][kb + ct + 4]);
                        mma8(acc[0][nf], a[0], b0, b1);
                        mma8(acc[1][nf], a[1], b0, b1);
                    }
                }
            }
        }
    }

    // ------------------------- epilogue -------------------------
    if (WAVELET) {
        const bool lower = (ct & 1) == 0;       // holds (ll,lh); else (hl,hh)
        #pragma unroll
        for (int mf = 0; mf < 2; ++mf) {
            #pragma unroll
            for (int half = 0; half < 2; ++half) {
                const int m = wm * 32 + mf * 16 + gr + half * 8;
                #pragma unroll
                for (int nf = 0; nf < NF; ++nf) {
                    const int colb = wn * (NF * 8) + nf * 8 + 2 * ct;
                    const int q = mt * 32 + (colb >> 2);
                    float v0 = acc[mf][nf][half * 2 + 0] + bias[(lower ? 0 : 128) + q];
                    float v1 = acc[mf][nf][half * 2 + 1] + bias[(lower ? 64 : 192) + q];
                    float s = v0 + v1, d = v0 - v1;
                    float so = __shfl_xor_sync(0xffffffffu, s, 1);
                    float dd = __shfl_xor_sync(0xffffffffu, d, 1);
                    float r0, r1;
                    int yy;
                    if (lower) { r0 = 0.5f * (s + so);  r1 = 0.5f * (d + dd);  yy = 2 * h; }
                    else       { r0 = 0.5f * (so - s);  r1 = 0.5f * (dd - d);  yy = 2 * h + 1; }
                    float* dst = g_up + (((size_t)b * CI + q) * 256 + yy) * 256 + 2 * m;
                    *(float2*)dst = make_float2(r0, r1);
                }
            }
        }
    } else {
        #pragma unroll
        for (int mf = 0; mf < 2; ++mf) {
            #pragma unroll
            for (int half = 0; half < 2; ++half) {
                const int m = wm * 32 + mf * 16 + gr + half * 8;
                const int x = px0 + m;
                #pragma unroll
                for (int nf = 0; nf < NF; ++nf) {
                    const int ch = wn * (NF * 8) + nf * 8 + 2 * ct;
                    outp[((size_t)(b * CI + ch) * 256 + h) * 256 + x] =
                        acc[mf][nf][half * 2 + 0] + bias[ch];
                    outp[((size_t)(b * CI + ch + 1) * 256 + h) * 256 + x] =
                        acc[mf][nf][half * 2 + 1] + bias[ch + 1];
                }
            }
        }
    }
}

extern "C" void kernel_launch(void* const* d_in, const int* in_sizes, int n_in,
                              void* d_out, int out_size)
{
    (void)in_sizes; (void)n_in; (void)out_size;
    const float* x      = (const float*)d_in[0];
    const float* w_pre  = (const float*)d_in[1];
    const float* b_pre  = (const float*)d_in[2];
    const float* w_post = (const float*)d_in[3];
    const float* b_post = (const float*)d_in[4];
    float* out = (float*)d_out;

    reorder_pre <<<(256 * KTOT + 255) / 256, 256>>>(w_pre);
    reorder_post<<<(64 * KTOT + 255) / 256, 256>>>(w_post);

    // conv_pre + wavelet -> g_up : rows of 128 px, channel halves in z
    conv_mma<128, 128, 128, 8, true><<<dim3(128, NB, 2), 256>>>(x, b_pre, nullptr);
    // conv_post : rows of 256 px (2 segments in z), all 64 channels
    conv_mma<256, 256, 64, 4, false><<<dim3(256, NB, 2), 256>>>(nullptr, b_post, out);
}

// round 6
// speedup vs baseline: 5.6355x; 1.0901x over previous
#include <cuda_runtime.h>
#include <cstdint>

#define NB 16
#define CI 64
#define KTOT 576     // 9 taps * 64 cin
#define NT  64       // N tile (channel rows per block)

// ---------------- device scratch (no allocs allowed) ----------------
__device__ float g_up[(size_t)NB * CI * 256 * 256];     // 256 MB intermediate
__device__ float g_wpre_hi[256 * KTOT];                 // quad-interleaved rows
__device__ float g_wpre_lo[256 * KTOT];
__device__ float g_wpost_hi[64 * KTOT];
__device__ float g_wpost_lo[64 * KTOT];

__device__ __forceinline__ uint32_t tf32r(float x) {
    uint32_t r; asm("cvt.rna.tf32.f32 %0, %1;" : "=r"(r) : "f"(x)); return r;
}

// m16n8k8 tf32 MMA, fp32 accumulate (sm_80+ baseline -> tensor pipe)
__device__ __forceinline__ void mma8(float* c, const uint32_t a[4],
                                     uint32_t b0, uint32_t b1) {
    asm volatile(
        "mma.sync.aligned.m16n8k8.row.col.f32.tf32.tf32.f32 "
        "{%0,%1,%2,%3}, {%4,%5,%6,%7}, {%8,%9}, {%0,%1,%2,%3};"
        : "+f"(c[0]), "+f"(c[1]), "+f"(c[2]), "+f"(c[3])
        : "r"(a[0]), "r"(a[1]), "r"(a[2]), "r"(a[3]), "r"(b0), "r"(b1));
}

// ---------------- weight reorder + hi/lo tf32 split ----------------
// pre rows: R = 4q+s  <->  conv channel ch = s*64+q ; k = tap*64 + cin
__global__ void reorder_pre(const float* __restrict__ w) {
    int i = blockIdx.x * blockDim.x + threadIdx.x;
    if (i >= 256 * KTOT) return;
    int k = i % KTOT, R = i / KTOT;
    int t = k / 64, ci = k % 64;
    int ch = (R & 3) * 64 + (R >> 2);
    float v = w[((ch * 64 + ci) * 3 + t / 3) * 3 + (t % 3)];
    float hi = __uint_as_float(tf32r(v));
    g_wpre_hi[i] = hi;
    g_wpre_lo[i] = __uint_as_float(tf32r(v - hi));
}
__global__ void reorder_post(const float* __restrict__ w) {
    int i = blockIdx.x * blockDim.x + threadIdx.x;
    if (i >= 64 * KTOT) return;
    int k = i % KTOT, co = i / KTOT;
    int t = k / 64, ci = k % 64;
    float v = w[((co * 64 + ci) * 3 + t / 3) * 3 + (t % 3)];
    float hi = __uint_as_float(tf32r(v));
    g_wpost_hi[i] = hi;
    g_wpost_lo[i] = __uint_as_float(tf32r(v - hi));
}

// ---------------- smem geometry ----------------
#define SIN_STRIDE 136          // floats per (row,ci) line; 136 mod 32 = 8 -> A banks 8ct+gr distinct
#define SIN_FLOATS (3 * 16 * SIN_STRIDE)          // 6528 floats = 26112 B
#define SW_PAD 68               // float2 stride; bank = 8ct+2gr -> phase-conflict-free
#define SW_F2   (144 * SW_PAD)                    // 9792 float2 = 78336 B
#define SMEM_BYTES (SIN_FLOATS * 4 + SW_F2 * 8)   // 104448 B

// ---------------------------------------------------------------------------
// Implicit-GEMM conv via warp mma.sync (tf32, hi/lo weight split).
// Block: 8 warps (4 m-warps x 2 n-warps). M = 128 px of one row, N = 64.
// Per cin-chunk (16): stage 3 input rows + ALL 9 taps' weights, then
// 9*2*16 MMAs with only 2 syncs per chunk.
// ---------------------------------------------------------------------------
template<int W, int H, bool WAVELET>
__global__ __launch_bounds__(256, 2)
void conv_mma(const float* __restrict__ xin, const float* __restrict__ bias,
              float* __restrict__ outp)
{
    extern __shared__ float smem[];
    float*  sIn = smem;                       // [3][16][SIN_STRIDE]
    float2* sW2 = (float2*)(smem + SIN_FLOATS); // [144][SW_PAD]  (hi,lo)

    const int tid  = threadIdx.x;
    const int lane = tid & 31;
    const int wid  = tid >> 5;
    const int wm   = wid & 3;              // m-warp: 32 px
    const int wn   = wid >> 2;             // n-warp: 32 ch
    const int gr   = lane >> 2;
    const int ct   = lane & 3;

    const int h  = blockIdx.x;
    const int b  = blockIdx.y;
    const int z  = blockIdx.z;
    const int px0 = WAVELET ? 0 : z * 128;   // post: pixel segment
    const int mt  = WAVELET ? z : 0;         // pre: n-tile (16 quads)

    const float* src = WAVELET ? xin : (const float*)g_up;
    const float* whi = WAVELET ? (g_wpre_hi + (size_t)mt * NT * KTOT) : g_wpost_hi;
    const float* wlo = WAVELET ? (g_wpre_lo + (size_t)mt * NT * KTOT) : g_wpost_lo;

    float acc[2][4][4];
    #pragma unroll
    for (int mf = 0; mf < 2; ++mf)
        #pragma unroll
        for (int nf = 0; nf < 4; ++nf)
            #pragma unroll
            for (int u = 0; u < 4; ++u) acc[mf][nf][u] = 0.0f;

    for (int c0 = 0; c0 < CI; c0 += 16) {
        __syncthreads();
        // ---- stage 3 input rows x 16 cins (tf32-rounded) ----
        for (int i = tid; i < 3 * 16 * 130; i += 256) {
            int p  = i % 130;
            int t2 = i / 130;
            int ci = t2 % 16;
            int r  = t2 / 16;
            int gh = h - 1 + r;
            int gw = px0 - 1 + p;
            float v = 0.0f;
            if (gh >= 0 && gh < H && gw >= 0 && gw < W)
                v = __ldg(&src[(((size_t)b * CI + c0 + ci) * H + gh) * (size_t)W + gw]);
            sIn[(r * 16 + ci) * SIN_STRIDE + p] = __uint_as_float(tf32r(v));
        }
        // ---- stage ALL 9 taps' weights for this chunk: (hi,lo) pairs ----
        // i -> k' (0..15, gmem-contiguous), n (0..63), t (0..8)
        for (int i = tid; i < NT * 144; i += 256) {
            int kp = i & 15;
            int n  = (i >> 4) & 63;
            int t  = i >> 10;
            size_t gidx = (size_t)n * KTOT + t * 64 + c0 + kp;
            sW2[(t * 16 + kp) * SW_PAD + n] =
                make_float2(__ldg(&whi[gidx]), __ldg(&wlo[gidx]));
        }
        __syncthreads();

        // ---- compute: 9 taps x 2 k-halves x 16 MMAs ----
        #pragma unroll
        for (int t = 0; t < 9; ++t) {
            const int rr  = t / 3;
            const int dwp = t % 3;
            const float* sRow0 = &sIn[(rr * 16 + ct) * SIN_STRIDE];
            const float* sRow4 = &sIn[(rr * 16 + ct + 4) * SIN_STRIDE];
            #pragma unroll
            for (int ks = 0; ks < 2; ++ks) {
                const int kb = ks * 8;
                uint32_t a[2][4];
                #pragma unroll
                for (int mf = 0; mf < 2; ++mf) {
                    const int px = wm * 32 + mf * 16 + gr + dwp;
                    a[mf][0] = __float_as_uint(sRow0[kb * SIN_STRIDE + px]);
                    a[mf][1] = __float_as_uint(sRow0[kb * SIN_STRIDE + px + 8]);
                    a[mf][2] = __float_as_uint(sRow4[kb * SIN_STRIDE + px]);
                    a[mf][3] = __float_as_uint(sRow4[kb * SIN_STRIDE + px + 8]);
                }
                const float2* wk0 = &sW2[(t * 16 + kb + ct) * SW_PAD];
                const float2* wk4 = &sW2[(t * 16 + kb + ct + 4) * SW_PAD];
                #pragma unroll
                for (int nf = 0; nf < 4; ++nf) {
                    const int n = wn * 32 + nf * 8 + gr;
                    float2 p0 = wk0[n];       // (hi, lo) at k = kb+ct
                    float2 p1 = wk4[n];       // (hi, lo) at k = kb+ct+4
                    uint32_t b0h = __float_as_uint(p0.x), b1h = __float_as_uint(p1.x);
                    uint32_t b0l = __float_as_uint(p0.y), b1l = __float_as_uint(p1.y);
                    mma8(acc[0][nf], a[0], b0h, b1h);
                    mma8(acc[1][nf], a[1], b0h, b1h);
                    mma8(acc[0][nf], a[0], b0l, b1l);
                    mma8(acc[1][nf], a[1], b0l, b1l);
                }
            }
        }
    }

    // ------------------------- epilogue -------------------------
    if (WAVELET) {
        const bool lower = (ct & 1) == 0;       // holds (ll,lh); else (hl,hh)
        #pragma unroll
        for (int mf = 0; mf < 2; ++mf) {
            #pragma unroll
            for (int half = 0; half < 2; ++half) {
                const int m = wm * 32 + mf * 16 + gr + half * 8;
                #pragma unroll
                for (int nf = 0; nf < 4; ++nf) {
                    const int colb = wn * 32 + nf * 8 + 2 * ct;
                    const int q = mt * 16 + (colb >> 2);
                    float v0 = acc[mf][nf][half * 2 + 0] + bias[(lower ? 0 : 128) + q];
                    float v1 = acc[mf][nf][half * 2 + 1] + bias[(lower ? 64 : 192) + q];
                    float s = v0 + v1, d = v0 - v1;
                    float so = __shfl_xor_sync(0xffffffffu, s, 1);
                    float dd = __shfl_xor_sync(0xffffffffu, d, 1);
                    float r0, r1;
                    int yy;
                    if (lower) { r0 = 0.5f * (s + so);  r1 = 0.5f * (d + dd);  yy = 2 * h; }
                    else       { r0 = 0.5f * (so - s);  r1 = 0.5f * (dd - d);  yy = 2 * h + 1; }
                    float* dst = g_up + (((size_t)b * CI + q) * 256 + yy) * 256 + 2 * m;
                    *(float2*)dst = make_float2(r0, r1);
                }
            }
        }
    } else {
        #pragma unroll
        for (int mf = 0; mf < 2; ++mf) {
            #pragma unroll
            for (int half = 0; half < 2; ++half) {
                const int m = wm * 32 + mf * 16 + gr + half * 8;
                const int x = px0 + m;
                #pragma unroll
                for (int nf = 0; nf < 4; ++nf) {
                    const int ch = wn * 32 + nf * 8 + 2 * ct;
                    outp[((size_t)(b * CI + ch) * 256 + h) * 256 + x] =
                        acc[mf][nf][half * 2 + 0] + bias[ch];
                    outp[((size_t)(b * CI + ch + 1) * 256 + h) * 256 + x] =
                        acc[mf][nf][half * 2 + 1] + bias[ch + 1];
                }
            }
        }
    }
}

extern "C" void kernel_launch(void* const* d_in, const int* in_sizes, int n_in,
                              void* d_out, int out_size)
{
    (void)in_sizes; (void)n_in; (void)out_size;
    const float* x      = (const float*)d_in[0];
    const float* w_pre  = (const float*)d_in[1];
    const float* b_pre  = (const float*)d_in[2];
    const float* w_post = (const float*)d_in[3];
    const float* b_post = (const float*)d_in[4];
    float* out = (float*)d_out;

    static int attr_done = 0;
    if (!attr_done) {
        cudaFuncSetAttribute(conv_mma<128, 128, true>,
                             cudaFuncAttributeMaxDynamicSharedMemorySize, SMEM_BYTES);
        cudaFuncSetAttribute(conv_mma<256, 256, false>,
                             cudaFuncAttributeMaxDynamicSharedMemorySize, SMEM_BYTES);
        attr_done = 1;
    }

    reorder_pre <<<(256 * KTOT + 255) / 256, 256>>>(w_pre);
    reorder_post<<<(64 * KTOT + 255) / 256, 256>>>(w_post);

    // conv_pre + wavelet -> g_up : rows of 128 px, 4 channel n-tiles in z
    conv_mma<128, 128, true>
        <<<dim3(128, NB, 4), 256, SMEM_BYTES>>>(x, b_pre, nullptr);
    // conv_post : rows of 256 px (2 segments in z), 64 channels
    conv_mma<256, 256, false>
        <<<dim3(256, NB, 2), 256, SMEM_BYTES>>>(nullptr, b_post, out);
}

// round 7
// speedup vs baseline: 7.1966x; 1.2770x over previous
#include <cuda_runtime.h>
#include <cstdint>

#define NB 16
#define CI 64
#define KTOT 576     // 9 taps * 64 cin
#define NT  64       // N tile (channel rows per block)

// ---------------- device scratch (no allocs allowed) ----------------
__device__ float g_up[(size_t)NB * CI * 256 * 256];     // 256 MB intermediate
__device__ float g_wpre [256 * KTOT];                   // quad-interleaved rows, tf32-rounded
__device__ float g_wpost[64 * KTOT];

__device__ __forceinline__ uint32_t tf32r(float x) {
    uint32_t r; asm("cvt.rna.tf32.f32 %0, %1;" : "=r"(r) : "f"(x)); return r;
}

// m16n8k8 tf32 MMA, fp32 accumulate (sm_80+ baseline -> tensor pipe)
__device__ __forceinline__ void mma8(float* c, const uint32_t a[4],
                                     uint32_t b0, uint32_t b1) {
    asm volatile(
        "mma.sync.aligned.m16n8k8.row.col.f32.tf32.tf32.f32 "
        "{%0,%1,%2,%3}, {%4,%5,%6,%7}, {%8,%9}, {%0,%1,%2,%3};"
        : "+f"(c[0]), "+f"(c[1]), "+f"(c[2]), "+f"(c[3])
        : "r"(a[0]), "r"(a[1]), "r"(a[2]), "r"(a[3]), "r"(b0), "r"(b1));
}

// ---------------- weight reorder (tf32-rounded, single copy) ----------------
// pre rows: R = 4q+s  <->  conv channel ch = s*64+q ; k = tap*64 + cin
__global__ void reorder_pre(const float* __restrict__ w) {
    int i = blockIdx.x * blockDim.x + threadIdx.x;
    if (i >= 256 * KTOT) return;
    int k = i % KTOT, R = i / KTOT;
    int t = k / 64, ci = k % 64;
    int ch = (R & 3) * 64 + (R >> 2);
    float v = w[((ch * 64 + ci) * 3 + t / 3) * 3 + (t % 3)];
    g_wpre[i] = __uint_as_float(tf32r(v));
}
__global__ void reorder_post(const float* __restrict__ w) {
    int i = blockIdx.x * blockDim.x + threadIdx.x;
    if (i >= 64 * KTOT) return;
    int k = i % KTOT, co = i / KTOT;
    int t = k / 64, ci = k % 64;
    float v = w[((co * 64 + ci) * 3 + t / 3) * 3 + (t % 3)];
    g_wpost[i] = __uint_as_float(tf32r(v));
}

// ---------------- smem geometry ----------------
#define SIN_STRIDE 136          // 136 mod 32 = 8 -> A banks 8ct+gr all distinct
#define SIN_FLOATS (3 * 16 * SIN_STRIDE)          // 26112 B
#define SW_PAD 68               // float stride; 68 mod 32 = 4 -> B banks 4ct+gr all distinct
#define SW_FLOATS (144 * SW_PAD)                  // 39168 B
#define SMEM_BYTES ((SIN_FLOATS + SW_FLOATS) * 4) // 65280 B

// ---------------------------------------------------------------------------
// Implicit-GEMM conv via warp mma.sync (tf32, single pass — both operands
// tf32-rounded). Block: 8 warps (4 m x 2 n). M = 128 px of one row, N = 64.
// Per cin-chunk (16): stage 3 input rows + all 9 taps' weights, 2 syncs.
// ---------------------------------------------------------------------------
template<int W, int H, bool WAVELET>
__global__ __launch_bounds__(256, 2)
void conv_mma(const float* __restrict__ xin, const float* __restrict__ bias,
              float* __restrict__ outp)
{
    extern __shared__ float smem[];
    float* sIn = smem;                    // [3][16][SIN_STRIDE]
    float* sW  = smem + SIN_FLOATS;       // [144][SW_PAD]

    const int tid  = threadIdx.x;
    const int lane = tid & 31;
    const int wid  = tid >> 5;
    const int wm   = wid & 3;             // m-warp: 32 px
    const int wn   = wid >> 2;            // n-warp: 32 ch
    const int gr   = lane >> 2;
    const int ct   = lane & 3;

    const int h  = blockIdx.x;
    const int b  = blockIdx.y;
    const int z  = blockIdx.z;
    const int px0 = WAVELET ? 0 : z * 128;
    const int mt  = WAVELET ? z : 0;

    const float* src = WAVELET ? xin : (const float*)g_up;
    const float* wsrc = WAVELET ? (g_wpre + (size_t)mt * NT * KTOT) : g_wpost;

    float acc[2][4][4];
    #pragma unroll
    for (int mf = 0; mf < 2; ++mf)
        #pragma unroll
        for (int nf = 0; nf < 4; ++nf)
            #pragma unroll
            for (int u = 0; u < 4; ++u) acc[mf][nf][u] = 0.0f;

    for (int c0 = 0; c0 < CI; c0 += 16) {
        __syncthreads();
        // ---- stage 3 input rows x 16 cins (tf32-rounded) ----
        for (int i = tid; i < 3 * 16 * 130; i += 256) {
            int p  = i % 130;
            int t2 = i / 130;
            int ci = t2 % 16;
            int r  = t2 / 16;
            int gh = h - 1 + r;
            int gw = px0 - 1 + p;
            float v = 0.0f;
            if (gh >= 0 && gh < H && gw >= 0 && gw < W)
                v = __ldg(&src[(((size_t)b * CI + c0 + ci) * H + gh) * (size_t)W + gw]);
            sIn[(r * 16 + ci) * SIN_STRIDE + p] = __uint_as_float(tf32r(v));
        }
        // ---- stage ALL 9 taps' weights for this chunk ----
        for (int i = tid; i < NT * 144; i += 256) {
            int kp = i & 15;
            int n  = (i >> 4) & 63;
            int t  = i >> 10;
            sW[(t * 16 + kp) * SW_PAD + n] =
                __ldg(&wsrc[(size_t)n * KTOT + t * 64 + c0 + kp]);
        }
        __syncthreads();

        // ---- compute: 9 taps x 2 k-halves x 8 MMAs ----
        #pragma unroll
        for (int t = 0; t < 9; ++t) {
            const int rr  = t / 3;
            const int dwp = t % 3;
            const float* sRow0 = &sIn[(rr * 16 + ct) * SIN_STRIDE];
            const float* sRow4 = &sIn[(rr * 16 + ct + 4) * SIN_STRIDE];
            #pragma unroll
            for (int ks = 0; ks < 2; ++ks) {
                const int kb = ks * 8;
                uint32_t a[2][4];
                #pragma unroll
                for (int mf = 0; mf < 2; ++mf) {
                    const int px = wm * 32 + mf * 16 + gr + dwp;
                    a[mf][0] = __float_as_uint(sRow0[kb * SIN_STRIDE + px]);
                    a[mf][1] = __float_as_uint(sRow0[kb * SIN_STRIDE + px + 8]);
                    a[mf][2] = __float_as_uint(sRow4[kb * SIN_STRIDE + px]);
                    a[mf][3] = __float_as_uint(sRow4[kb * SIN_STRIDE + px + 8]);
                }
                const float* wk0 = &sW[(t * 16 + kb + ct) * SW_PAD];
                const float* wk4 = &sW[(t * 16 + kb + ct + 4) * SW_PAD];
                #pragma unroll
                for (int nf = 0; nf < 4; ++nf) {
                    const int n = wn * 32 + nf * 8 + gr;
                    uint32_t b0 = __float_as_uint(wk0[n]);
                    uint32_t b1 = __float_as_uint(wk4[n]);
                    mma8(acc[0][nf], a[0], b0, b1);
                    mma8(acc[1][nf], a[1], b0, b1);
                }
            }
        }
    }

    // ------------------------- epilogue -------------------------
    if (WAVELET) {
        const bool lower = (ct & 1) == 0;       // holds (ll,lh); else (hl,hh)
        #pragma unroll
        for (int mf = 0; mf < 2; ++mf) {
            #pragma unroll
            for (int half = 0; half < 2; ++half) {
                const int m = wm * 32 + mf * 16 + gr + half * 8;
                #pragma unroll
                for (int nf = 0; nf < 4; ++nf) {
                    const int colb = wn * 32 + nf * 8 + 2 * ct;
                    const int q = mt * 16 + (colb >> 2);
                    float v0 = acc[mf][nf][half * 2 + 0] + bias[(lower ? 0 : 128) + q];
                    float v1 = acc[mf][nf][half * 2 + 1] + bias[(lower ? 64 : 192) + q];
                    float s = v0 + v1, d = v0 - v1;
                    float so = __shfl_xor_sync(0xffffffffu, s, 1);
                    float dd = __shfl_xor_sync(0xffffffffu, d, 1);
                    float r0, r1;
                    int yy;
                    if (lower) { r0 = 0.5f * (s + so);  r1 = 0.5f * (d + dd);  yy = 2 * h; }
                    else       { r0 = 0.5f * (so - s);  r1 = 0.5f * (dd - d);  yy = 2 * h + 1; }
                    float* dst = g_up + (((size_t)b * CI + q) * 256 + yy) * 256 + 2 * m;
                    *(float2*)dst = make_float2(r0, r1);
                }
            }
        }
    } else {
        #pragma unroll
        for (int mf = 0; mf < 2; ++mf) {
            #pragma unroll
            for (int half = 0; half < 2; ++half) {
                const int m = wm * 32 + mf * 16 + gr + half * 8;
                const int x = px0 + m;
                #pragma unroll
                for (int nf = 0; nf < 4; ++nf) {
                    const int ch = wn * 32 + nf * 8 + 2 * ct;
                    outp[((size_t)(b * CI + ch) * 256 + h) * 256 + x] =
                        acc[mf][nf][half * 2 + 0] + bias[ch];
                    outp[((size_t)(b * CI + ch + 1) * 256 + h) * 256 + x] =
                        acc[mf][nf][half * 2 + 1] + bias[ch + 1];
                }
            }
        }
    }
}

extern "C" void kernel_launch(void* const* d_in, const int* in_sizes, int n_in,
                              void* d_out, int out_size)
{
    (void)in_sizes; (void)n_in; (void)out_size;
    const float* x      = (const float*)d_in[0];
    const float* w_pre  = (const float*)d_in[1];
    const float* b_pre  = (const float*)d_in[2];
    const float* w_post = (const float*)d_in[3];
    const float* b_post = (const float*)d_in[4];
    float* out = (float*)d_out;

    static int attr_done = 0;
    if (!attr_done) {
        cudaFuncSetAttribute(conv_mma<128, 128, true>,
                             cudaFuncAttributeMaxDynamicSharedMemorySize, SMEM_BYTES);
        cudaFuncSetAttribute(conv_mma<256, 256, false>,
                             cudaFuncAttributeMaxDynamicSharedMemorySize, SMEM_BYTES);
        attr_done = 1;
    }

    reorder_pre <<<(256 * KTOT + 255) / 256, 256>>>(w_pre);
    reorder_post<<<(64 * KTOT + 255) / 256, 256>>>(w_post);

    // conv_pre + wavelet -> g_up : rows of 128 px, 4 channel n-tiles in z
    conv_mma<128, 128, true>
        <<<dim3(128, NB, 4), 256, SMEM_BYTES>>>(x, b_pre, nullptr);
    // conv_post : rows of 256 px (2 segments in z), 64 channels
    conv_mma<256, 256, false>
        <<<dim3(256, NB, 2), 256, SMEM_BYTES>>>(nullptr, b_post, out);
}

// round 8
// speedup vs baseline: 9.9090x; 1.3769x over previous
#include <cuda_runtime.h>
#include <cstdint>

#define NB 16
#define CI 64
#define KTOT 576     // 9 taps * 64 cin
#define NT  64       // N tile (channel rows per block)
#define CHB 9216     // floats per (chunk) weight block: 9*16*64

// ---------------- device scratch (no allocs allowed) ----------------
__device__ float g_up[(size_t)NB * CI * 256 * 256];     // 256 MB intermediate
__device__ float g_wpre [4 * 4 * CHB];                  // [mt][chunk][t][kp][n'] tf32
__device__ float g_wpost[4 * CHB];                      // [chunk][t][kp][n'] tf32

__device__ __forceinline__ uint32_t tf32r(float x) {
    uint32_t r; asm("cvt.rna.tf32.f32 %0, %1;" : "=r"(r) : "f"(x)); return r;
}

// m16n8k8 tf32 MMA, fp32 accumulate (sm_80+ baseline -> tensor pipe)
__device__ __forceinline__ void mma8(float* c, const uint32_t a[4],
                                     uint32_t b0, uint32_t b1) {
    asm volatile(
        "mma.sync.aligned.m16n8k8.row.col.f32.tf32.tf32.f32 "
        "{%0,%1,%2,%3}, {%4,%5,%6,%7}, {%8,%9}, {%0,%1,%2,%3};"
        : "+f"(c[0]), "+f"(c[1]), "+f"(c[2]), "+f"(c[3])
        : "r"(a[0]), "r"(a[1]), "r"(a[2]), "r"(a[3]), "r"(b0), "r"(b1));
}

// inverse of the n-permutation n' = (n&7)*4 + ((n>>3)&3) + (n>>5)*32
__device__ __forceinline__ int inv_perm64(int np) {
    int block = np >> 5, w4 = (np & 31) >> 2, sub = np & 3;
    return block * 32 + sub * 8 + w4;
}

// ---------------- weight reorder: tf32-round + permute + chunk-major ----------------
// pre: n-tile mt rows R = mt*64+n ; ch = (R&3)*64 + (R>>2) ; k = tap*64 + cin
__global__ void reorder_pre(const float* __restrict__ w) {
    int o = blockIdx.x * blockDim.x + threadIdx.x;
    if (o >= 16 * CHB) return;
    int np = o & 63;
    int kp = (o >> 6) & 15;
    int t  = (o >> 10) % 9;
    int c  = (o / (9 * 16 * 64)) & 3;
    int mt = o / (4 * 9 * 16 * 64);
    int n  = inv_perm64(np);
    int R  = mt * 64 + n;
    int ch = (R & 3) * 64 + (R >> 2);
    int ci = c * 16 + kp;
    float v = w[((ch * 64 + ci) * 3 + t / 3) * 3 + (t % 3)];
    g_wpre[o] = __uint_as_float(tf32r(v));
}
__global__ void reorder_post(const float* __restrict__ w) {
    int o = blockIdx.x * blockDim.x + threadIdx.x;
    if (o >= 4 * CHB) return;
    int np = o & 63;
    int kp = (o >> 6) & 15;
    int t  = (o >> 10) % 9;
    int c  = o / (9 * 16 * 64);
    int co = inv_perm64(np);
    int ci = c * 16 + kp;
    float v = w[((co * 64 + ci) * 3 + t / 3) * 3 + (t % 3)];
    g_wpost[o] = __uint_as_float(tf32r(v));
}

// ---------------- smem geometry ----------------
// A: [NR*16 lines][STRIDE]; STRIDE mod 32 == 8 -> A banks 8ct+gr distinct
// B: [144 k-lines][72]; 72 mod 32 == 8 -> LDS.128 banks 8ct+4gr+j distinct
#define SWSTR 72

// ---------------------------------------------------------------------------
// Implicit-GEMM conv, warp mma.sync tf32. Block: 8 warps, each 32px x 64ch
// (mf=2, nf=8). Pre: block = 2 image rows x 128px, 4 n-tiles in z.
// Post: block = 1 row x 256px. Per cin-chunk: 2 syncs.
// ---------------------------------------------------------------------------
template<int W, int H, int STRIDE, bool WAVELET>
__global__ __launch_bounds__(256, 2)
void conv_mma(const float* __restrict__ xin, const float* __restrict__ bias,
              float* __restrict__ outp)
{
    constexpr int NR = WAVELET ? 4 : 3;      // staged input rows
    constexpr int PR = W + 2;                // staged pixels per line
    extern __shared__ float smem[];
    float* sIn = smem;                        // [NR*16][STRIDE]
    float* sW  = smem + NR * 16 * STRIDE;     // [144][SWSTR]

    const int tid  = threadIdx.x;
    const int lane = tid & 31;
    const int wid  = tid >> 5;
    const int gr   = lane >> 2;
    const int ct   = lane & 3;
    const int wm     = WAVELET ? (wid & 3) : wid;   // px segment of 32
    const int rowsel = WAVELET ? (wid >> 2) : 0;    // image row within block

    const int h0 = WAVELET ? 2 * blockIdx.x : blockIdx.x;
    const int b  = blockIdx.y;
    const int mt = WAVELET ? blockIdx.z : 0;

    const float* src  = WAVELET ? xin : (const float*)g_up;
    const float* wsrc = WAVELET ? (g_wpre + (size_t)mt * 4 * CHB) : g_wpost;

    float acc[2][8][4];
    #pragma unroll
    for (int mf = 0; mf < 2; ++mf)
        #pragma unroll
        for (int j = 0; j < 8; ++j)
            #pragma unroll
            for (int u = 0; u < 4; ++u) acc[mf][j][u] = 0.0f;

    for (int cc = 0; cc < 4; ++cc) {         // cin chunks of 16
        __syncthreads();
        // ---- A staging: NR rows x 16 cins (tf32-rounded) ----
        for (int i = tid; i < NR * 16 * PR; i += 256) {
            int p  = i % PR;
            int t2 = i / PR;
            int ci = t2 & 15;
            int r  = t2 >> 4;
            int gh = h0 - 1 + r;
            int gw = p - 1;
            float v = 0.0f;
            if (gh >= 0 && gh < H && gw >= 0 && gw < W)
                v = __ldg(&src[(((size_t)b * CI + cc * 16 + ci) * H + gh) * (size_t)W + gw]);
            sIn[(r * 16 + ci) * STRIDE + p] = __uint_as_float(tf32r(v));
        }
        // ---- B staging: straight conflict-free copy (pre-permuted) ----
        {
            const float* wp = wsrc + (size_t)cc * CHB;
            for (int i = tid; i < CHB; i += 256) {
                int np = i & 63;
                int kl = i >> 6;              // t*16 + kp
                sW[kl * SWSTR + np] = __ldg(&wp[i]);
            }
        }
        __syncthreads();

        // ---- compute: 9 taps x 2 k-halves x 16 MMAs ----
        #pragma unroll
        for (int t = 0; t < 9; ++t) {
            const int rr  = rowsel + t / 3;
            const int dwp = t % 3;
            #pragma unroll
            for (int ks = 0; ks < 2; ++ks) {
                const int kb = ks * 8;
                uint32_t a[2][4];
                #pragma unroll
                for (int mf = 0; mf < 2; ++mf) {
                    const int px = wm * 32 + mf * 16 + gr + dwp;
                    const float* l0 = &sIn[(rr * 16 + kb + ct) * STRIDE];
                    const float* l4 = &sIn[(rr * 16 + kb + ct + 4) * STRIDE];
                    a[mf][0] = __float_as_uint(l0[px]);
                    a[mf][1] = __float_as_uint(l0[px + 8]);
                    a[mf][2] = __float_as_uint(l4[px]);
                    a[mf][3] = __float_as_uint(l4[px + 8]);
                }
                const float* bk0 = &sW[(t * 16 + kb + ct) * SWSTR];
                const float* bk1 = &sW[(t * 16 + kb + ct + 4) * SWSTR];
                float4 B0[2], B1[2];
                B0[0] = *(const float4*)&bk0[gr * 4];
                B0[1] = *(const float4*)&bk0[32 + gr * 4];
                B1[0] = *(const float4*)&bk1[gr * 4];
                B1[1] = *(const float4*)&bk1[32 + gr * 4];
                #pragma unroll
                for (int j = 0; j < 8; ++j) {
                    const float4& v0 = B0[j >> 2];
                    const float4& v1 = B1[j >> 2];
                    float f0 = (j & 2) ? ((j & 1) ? v0.w : v0.z)
                                       : ((j & 1) ? v0.y : v0.x);
                    float f1 = (j & 2) ? ((j & 1) ? v1.w : v1.z)
                                       : ((j & 1) ? v1.y : v1.x);
                    mma8(acc[0][j], a[0], __float_as_uint(f0), __float_as_uint(f1));
                    mma8(acc[1][j], a[1], __float_as_uint(f0), __float_as_uint(f1));
                }
            }
        }
    }

    // ------------------------- epilogue -------------------------
    if (WAVELET) {
        const int h = h0 + rowsel;
        const bool lower = (ct & 1) == 0;        // holds (ll,lh); else (hl,hh)
        #pragma unroll
        for (int mf = 0; mf < 2; ++mf) {
            #pragma unroll
            for (int half = 0; half < 2; ++half) {
                const int m = wm * 32 + mf * 16 + gr + half * 8;
                #pragma unroll
                for (int j = 0; j < 8; ++j) {
                    const int colb = j * 8 + 2 * ct;
                    const int q = mt * 16 + (colb >> 2);
                    float v0 = acc[mf][j][half * 2 + 0] + bias[(lower ? 0 : 128) + q];
                    float v1 = acc[mf][j][half * 2 + 1] + bias[(lower ? 64 : 192) + q];
                    float s = v0 + v1, d = v0 - v1;
                    float so = __shfl_xor_sync(0xffffffffu, s, 1);
                    float dd = __shfl_xor_sync(0xffffffffu, d, 1);
                    float r0, r1;
                    int yy;
                    if (lower) { r0 = 0.5f * (s + so);  r1 = 0.5f * (d + dd);  yy = 2 * h; }
                    else       { r0 = 0.5f * (so - s);  r1 = 0.5f * (dd - d);  yy = 2 * h + 1; }
                    float* dst = g_up + (((size_t)b * CI + q) * 256 + yy) * 256 + 2 * m;
                    *(float2*)dst = make_float2(r0, r1);
                }
            }
        }
    } else {
        #pragma unroll
        for (int mf = 0; mf < 2; ++mf) {
            #pragma unroll
            for (int half = 0; half < 2; ++half) {
                const int x = wm * 32 + mf * 16 + gr + half * 8;
                #pragma unroll
                for (int j = 0; j < 8; ++j) {
                    const int ch = j * 8 + 2 * ct;
                    outp[((size_t)(b * CI + ch) * 256 + h0) * 256 + x] =
                        acc[mf][j][half * 2 + 0] + bias[ch];
                    outp[((size_t)(b * CI + ch + 1) * 256 + h0) * 256 + x] =
                        acc[mf][j][half * 2 + 1] + bias[ch + 1];
                }
            }
        }
    }
}

#define SMEM_PRE  ((4 * 16 * 136 + 144 * SWSTR) * 4)   // 76288 B
#define SMEM_POST ((3 * 16 * 264 + 144 * SWSTR) * 4)   // 92160 B

extern "C" void kernel_launch(void* const* d_in, const int* in_sizes, int n_in,
                              void* d_out, int out_size)
{
    (void)in_sizes; (void)n_in; (void)out_size;
    const float* x      = (const float*)d_in[0];
    const float* w_pre  = (const float*)d_in[1];
    const float* b_pre  = (const float*)d_in[2];
    const float* w_post = (const float*)d_in[3];
    const float* b_post = (const float*)d_in[4];
    float* out = (float*)d_out;

    static int attr_done = 0;
    if (!attr_done) {
        cudaFuncSetAttribute(conv_mma<128, 128, 136, true>,
                             cudaFuncAttributeMaxDynamicSharedMemorySize, SMEM_PRE);
        cudaFuncSetAttribute(conv_mma<256, 256, 264, false>,
                             cudaFuncAttributeMaxDynamicSharedMemorySize, SMEM_POST);
        attr_done = 1;
    }

    reorder_pre <<<(16 * CHB + 255) / 256, 256>>>(w_pre);
    reorder_post<<<(4 * CHB + 255) / 256, 256>>>(w_post);

    // conv_pre + wavelet -> g_up : 2 rows x 128 px per block, 4 n-tiles in z
    conv_mma<128, 128, 136, true>
        <<<dim3(64, NB, 4), 256, SMEM_PRE>>>(x, b_pre, nullptr);
    // conv_post : 1 row x 256 px per block, 64 channels
    conv_mma<256, 256, 264, false>
        <<<dim3(256, NB, 1), 256, SMEM_POST>>>(nullptr, b_post, out);
}

// round 9
// speedup vs baseline: 9.9351x; 1.0026x over previous
#include <cuda_runtime.h>
#include <cstdint>

#define NB 16
#define CI 64
#define CHB 9216     // floats per chunk weight block: 9*16*64

// ---------------- device scratch (no allocs allowed) ----------------
__device__ float g_up[(size_t)NB * CI * 256 * 256];     // 256 MB, tf32-rounded
__device__ float g_x [(size_t)NB * CI * 128 * 128];     // 67 MB, tf32-rounded x
__device__ float g_wpre [4 * 4 * CHB];                  // [mt][chunk][t][kp][n']
__device__ float g_wpost[4 * CHB];                      // [chunk][t][kp][n']

__device__ __forceinline__ uint32_t tf32r(float x) {
    uint32_t r; asm("cvt.rna.tf32.f32 %0, %1;" : "=r"(r) : "f"(x)); return r;
}
__device__ __forceinline__ float tf32f(float x) { return __uint_as_float(tf32r(x)); }

__device__ __forceinline__ uint32_t smem_u32(const void* p) {
    uint32_t a;
    asm("{ .reg .u64 t; cvta.to.shared.u64 t, %1; cvt.u32.u64 %0, t; }" : "=r"(a) : "l"(p));
    return a;
}
__device__ __forceinline__ void cp16(uint32_t dst, const void* src, uint32_t sz) {
    asm volatile("cp.async.ca.shared.global [%0], [%1], 16, %2;"
                 :: "r"(dst), "l"(src), "r"(sz) : "memory");
}
#define CP_COMMIT() asm volatile("cp.async.commit_group;" ::: "memory")
#define CP_WAIT0()  asm volatile("cp.async.wait_group 0;" ::: "memory")

// m16n8k8 tf32 MMA, fp32 accumulate (sm_80+ baseline -> tensor pipe)
__device__ __forceinline__ void mma8(float* c, const uint32_t a[4],
                                     uint32_t b0, uint32_t b1) {
    asm volatile(
        "mma.sync.aligned.m16n8k8.row.col.f32.tf32.tf32.f32 "
        "{%0,%1,%2,%3}, {%4,%5,%6,%7}, {%8,%9}, {%0,%1,%2,%3};"
        : "+f"(c[0]), "+f"(c[1]), "+f"(c[2]), "+f"(c[3])
        : "r"(a[0]), "r"(a[1]), "r"(a[2]), "r"(a[3]), "r"(b0), "r"(b1));
}

// inverse of n-permutation n' = (n&7)*4 + ((n>>3)&3) + (n>>5)*32
__device__ __forceinline__ int inv_perm64(int np) {
    return (np >> 5) * 32 + (np & 3) * 8 + ((np & 31) >> 2);
}

// ---------------- prep kernels ----------------
__global__ void round_x(const float* __restrict__ x, int n) {
    int i = blockIdx.x * blockDim.x + threadIdx.x;
    if (i < n) g_x[i] = tf32f(x[i]);
}
__global__ void reorder_pre(const float* __restrict__ w) {
    int o = blockIdx.x * blockDim.x + threadIdx.x;
    if (o >= 16 * CHB) return;
    int np = o & 63;
    int kp = (o >> 6) & 15;
    int t  = (o >> 10) % 9;
    int c  = (o / (9 * 16 * 64)) & 3;
    int mt = o / (4 * 9 * 16 * 64);
    int R  = mt * 64 + inv_perm64(np);
    int ch = (R & 3) * 64 + (R >> 2);
    g_wpre[o] = tf32f(w[((ch * 64 + c * 16 + kp) * 3 + t / 3) * 3 + (t % 3)]);
}
__global__ void reorder_post(const float* __restrict__ w) {
    int o = blockIdx.x * blockDim.x + threadIdx.x;
    if (o >= 4 * CHB) return;
    int np = o & 63;
    int kp = (o >> 6) & 15;
    int t  = (o >> 10) % 9;
    int c  = o / (9 * 16 * 64);
    int co = inv_perm64(np);
    g_wpost[o] = tf32f(w[((co * 64 + c * 16 + kp) * 3 + t / 3) * 3 + (t % 3)]);
}

// ---------------------------------------------------------------------------
// Implicit-GEMM conv, warp mma.sync tf32, double-buffered cp.async A staging,
// B operands via direct LDG.128 from pre-permuted global (L1/L2-resident).
// Smem A line layout: p = gw + 4 for gw in [0,W); p=3 is gw=-1 (zero),
// p=W+4 is gw=W (zero). STRIDE mod 32 == 8 -> frag banks 8ct+gr+c distinct.
// ---------------------------------------------------------------------------
template<int W, int H, int STRIDE, bool WAVELET>
__global__ __launch_bounds__(256, 2)
void conv_mma(const float* __restrict__ bias, float* __restrict__ outp)
{
    constexpr int NR   = WAVELET ? 4 : 3;
    constexpr int LINES = NR * 16;
    constexpr int BUFN = LINES * STRIDE;            // floats per buffer
    extern __shared__ float smem[];
    const uint32_t sb = smem_u32(smem);

    const int tid  = threadIdx.x;
    const int lane = tid & 31;
    const int wid  = tid >> 5;
    const int gr   = lane >> 2;
    const int ct   = lane & 3;
    const int wm     = WAVELET ? (wid & 3) : wid;
    const int rowsel = WAVELET ? (wid >> 2) : 0;

    const int h0 = WAVELET ? 2 * blockIdx.x : blockIdx.x;
    const int b  = blockIdx.y;
    const int mt = WAVELET ? blockIdx.z : 0;

    const float* src  = WAVELET ? g_x : g_up;
    const float* wsrc = WAVELET ? (g_wpre + (size_t)mt * 4 * CHB) : g_wpost;

    // zero border cells (p=3, p=W+4) in both buffers
    for (int i = tid; i < 2 * LINES; i += 256) {
        int bf = i >= LINES, line = i - bf * LINES;
        smem[bf * BUFN + line * STRIDE + 3]     = 0.0f;
        smem[bf * BUFN + line * STRIDE + W + 4] = 0.0f;
    }
    __syncthreads();

    // stage chunk cc into buffer bf: pure cp.async, no div/mod
    auto stage = [&](int cc, int bf) {
        const uint32_t dbuf = sb + (uint32_t)bf * BUFN * 4u;
        #pragma unroll
        for (int line = wid; line < LINES; line += 8) {
            const int r  = line >> 4;
            const int ci = line & 15;
            const int gh = h0 - 1 + r;
            const uint32_t ok = (gh >= 0 && gh < H) ? 16u : 0u;
            const int ghc = (gh >= 0 && gh < H) ? gh : 0;
            const float* sp = src + ((size_t)(b * CI + cc * 16 + ci) * H + ghc) * W;
            const uint32_t db = dbuf + (uint32_t)(line * STRIDE + 4) * 4u;
            #pragma unroll
            for (int c = lane; c < W / 4; c += 32)
                cp16(db + c * 16u, sp + c * 4, ok);
        }
    };

    float acc[2][8][4];
    #pragma unroll
    for (int mf = 0; mf < 2; ++mf)
        #pragma unroll
        for (int j = 0; j < 8; ++j)
            #pragma unroll
            for (int u = 0; u < 4; ++u) acc[mf][j][u] = 0.0f;

    stage(0, 0);
    CP_COMMIT();

    for (int cc = 0; cc < 4; ++cc) {
        CP_WAIT0();
        __syncthreads();
        if (cc < 3) { stage(cc + 1, (cc + 1) & 1); CP_COMMIT(); }

        const float*  sIn = smem + (cc & 1) * BUFN;
        const float4* wb  = (const float4*)(wsrc + (size_t)cc * CHB);

        #pragma unroll
        for (int t = 0; t < 9; ++t) {
            const int rr  = rowsel + t / 3;
            const int dwp = t % 3;
            #pragma unroll
            for (int ks = 0; ks < 2; ++ks) {
                const int kb = ks * 8;
                uint32_t a[2][4];
                #pragma unroll
                for (int mf = 0; mf < 2; ++mf) {
                    const int px = wm * 32 + mf * 16 + gr + dwp + 3;
                    const float* l0 = &sIn[(rr * 16 + kb + ct) * STRIDE];
                    const float* l4 = &sIn[(rr * 16 + kb + ct + 4) * STRIDE];
                    a[mf][0] = __float_as_uint(l0[px]);
                    a[mf][1] = __float_as_uint(l0[px + 8]);
                    a[mf][2] = __float_as_uint(l4[px]);
                    a[mf][3] = __float_as_uint(l4[px + 8]);
                }
                // B: 4 x LDG.128, compile-time offsets from per-chunk base
                const int l0i = (t * 16 + kb + ct) * 16 + gr;
                const int l4i = (t * 16 + kb + ct + 4) * 16 + gr;
                float4 B0[2], B1[2];
                B0[0] = __ldg(&wb[l0i]);
                B0[1] = __ldg(&wb[l0i + 8]);
                B1[0] = __ldg(&wb[l4i]);
                B1[1] = __ldg(&wb[l4i + 8]);
                #pragma unroll
                for (int j = 0; j < 8; ++j) {
                    const float4& v0 = B0[j >> 2];
                    const float4& v1 = B1[j >> 2];
                    float f0 = (j & 2) ? ((j & 1) ? v0.w : v0.z)
                                       : ((j & 1) ? v0.y : v0.x);
                    float f1 = (j & 2) ? ((j & 1) ? v1.w : v1.z)
                                       : ((j & 1) ? v1.y : v1.x);
                    mma8(acc[0][j], a[0], __float_as_uint(f0), __float_as_uint(f1));
                    mma8(acc[1][j], a[1], __float_as_uint(f0), __float_as_uint(f1));
                }
            }
        }
    }

    // ------------------------- epilogue -------------------------
    if (WAVELET) {
        const int h = h0 + rowsel;
        const bool lower = (ct & 1) == 0;        // holds (ll,lh); else (hl,hh)
        #pragma unroll
        for (int mf = 0; mf < 2; ++mf) {
            #pragma unroll
            for (int half = 0; half < 2; ++half) {
                const int m = wm * 32 + mf * 16 + gr + half * 8;
                #pragma unroll
                for (int j = 0; j < 8; ++j) {
                    const int colb = j * 8 + 2 * ct;
                    const int q = mt * 16 + (colb >> 2);
                    float v0 = acc[mf][j][half * 2 + 0] + __ldg(&bias[(lower ? 0 : 128) + q]);
                    float v1 = acc[mf][j][half * 2 + 1] + __ldg(&bias[(lower ? 64 : 192) + q]);
                    float s = v0 + v1, d = v0 - v1;
                    float so = __shfl_xor_sync(0xffffffffu, s, 1);
                    float dd = __shfl_xor_sync(0xffffffffu, d, 1);
                    float r0, r1;
                    int yy;
                    if (lower) { r0 = 0.5f * (s + so);  r1 = 0.5f * (d + dd);  yy = 2 * h; }
                    else       { r0 = 0.5f * (so - s);  r1 = 0.5f * (dd - d);  yy = 2 * h + 1; }
                    float* dst = g_up + (((size_t)b * CI + q) * 256 + yy) * 256 + 2 * m;
                    *(float2*)dst = make_float2(tf32f(r0), tf32f(r1));   // pre-rounded for post
                }
            }
        }
    } else {
        #pragma unroll
        for (int mf = 0; mf < 2; ++mf) {
            #pragma unroll
            for (int half = 0; half < 2; ++half) {
                const int x = wm * 32 + mf * 16 + gr + half * 8;
                #pragma unroll
                for (int j = 0; j < 8; ++j) {
                    const int ch = j * 8 + 2 * ct;
                    outp[((size_t)(b * CI + ch) * 256 + h0) * 256 + x] =
                        acc[mf][j][half * 2 + 0] + __ldg(&bias[ch]);
                    outp[((size_t)(b * CI + ch + 1) * 256 + h0) * 256 + x] =
                        acc[mf][j][half * 2 + 1] + __ldg(&bias[ch + 1]);
                }
            }
        }
    }
}

#define SMEM_PRE  (2 * 4 * 16 * 136 * 4)   // 69632 B
#define SMEM_POST (2 * 3 * 16 * 264 * 4)   // 101376 B

extern "C" void kernel_launch(void* const* d_in, const int* in_sizes, int n_in,
                              void* d_out, int out_size)
{
    (void)in_sizes; (void)n_in; (void)out_size;
    const float* x      = (const float*)d_in[0];
    const float* w_pre  = (const float*)d_in[1];
    const float* b_pre  = (const float*)d_in[2];
    const float* w_post = (const float*)d_in[3];
    const float* b_post = (const float*)d_in[4];
    float* out = (float*)d_out;

    static int attr_done = 0;
    if (!attr_done) {
        cudaFuncSetAttribute(conv_mma<128, 128, 136, true>,
                             cudaFuncAttributeMaxDynamicSharedMemorySize, SMEM_PRE);
        cudaFuncSetAttribute(conv_mma<256, 256, 264, false>,
                             cudaFuncAttributeMaxDynamicSharedMemorySize, SMEM_POST);
        attr_done = 1;
    }

    const int nx = NB * CI * 128 * 128;
    round_x<<<(nx + 255) / 256, 256>>>(x, nx);
    reorder_pre <<<(16 * CHB + 255) / 256, 256>>>(w_pre);
    reorder_post<<<(4 * CHB + 255) / 256, 256>>>(w_post);

    // conv_pre + wavelet -> g_up : 2 rows x 128 px per block, 4 n-tiles in z
    conv_mma<128, 128, 136, true>
        <<<dim3(64, NB, 4), 256, SMEM_PRE>>>(b_pre, nullptr);
    // conv_post : 1 row x 256 px per block, 64 channels
    conv_mma<256, 256, 264, false>
        <<<dim3(256, NB, 1), 256, SMEM_POST>>>(b_post, out);
}